// round 3
// baseline (speedup 1.0000x reference)
#include <cuda_runtime.h>
#include <cuda_bf16.h>
#include <math.h>

// Problem constants
#define Hd     1024
#define Bd     64
#define Ld     256
#define KDIM   2048          // 2*H  (hl | hr)
#define NDIM   5120          // 5*H  (i | o | ck | fl | fr)
#define NLVL   8             // 256 -> 1
#define FOREST 255           // nodes per batch in forest_output

// ---- static device scratch (no allocations allowed) ----
__device__ float g_Wcat[(size_t)KDIM * NDIM];                 // packed weights (2048 x 5120)
__device__ float g_bcat[NDIM];                                // packed bias
__device__ float g_h0[(size_t)Bd * Ld * Hd];                  // level-0 input (embeddings)
__device__ float g_pre[(size_t)(Bd * Ld / 2) * NDIM];         // GEMM output, max M = 8192
__device__ float g_cbuf[2][(size_t)Bd * (Ld / 2) * Hd];       // c ping-pong

__device__ __forceinline__ float sigmoidf_(float x) {
    return 1.0f / (1.0f + expf(-x));
}

// ---------------------------------------------------------------------------
// 1) pack weights: Wcat[k][n]  (k<1024: W rows, else U rows; n: [iock|fl|fr])
// ---------------------------------------------------------------------------
__global__ void pack_weights_kernel(const float* __restrict__ W_iock,
                                    const float* __restrict__ U_iock,
                                    const float* __restrict__ W_fl,
                                    const float* __restrict__ U_fl,
                                    const float* __restrict__ W_fr,
                                    const float* __restrict__ U_fr,
                                    const float* __restrict__ b_iock,
                                    const float* __restrict__ b_fl,
                                    const float* __restrict__ b_fr) {
    size_t idx = (size_t)blockIdx.x * blockDim.x + threadIdx.x;
    if (idx >= (size_t)KDIM * NDIM) return;
    int n = (int)(idx % NDIM);
    int k = (int)(idx / NDIM);
    bool isW = (k < Hd);
    int kr = isW ? k : (k - Hd);
    float v;
    if (n < 3 * Hd) {
        v = isW ? W_iock[(size_t)kr * (3 * Hd) + n] : U_iock[(size_t)kr * (3 * Hd) + n];
    } else if (n < 4 * Hd) {
        int nn = n - 3 * Hd;
        v = isW ? W_fl[(size_t)kr * Hd + nn] : U_fl[(size_t)kr * Hd + nn];
    } else {
        int nn = n - 4 * Hd;
        v = isW ? W_fr[(size_t)kr * Hd + nn] : U_fr[(size_t)kr * Hd + nn];
    }
    g_Wcat[idx] = v;
    if (idx < NDIM) {
        int nb = (int)idx;
        g_bcat[nb] = (nb < 3 * Hd) ? b_iock[nb]
                   : (nb < 4 * Hd) ? b_fl[nb - 3 * Hd]
                                   : b_fr[nb - 4 * Hd];
    }
}

// ---------------------------------------------------------------------------
// 2) embedding gather: g_h0[b, l, :] = emb[tokens[b,l], :]   (float4 vectorized)
// ---------------------------------------------------------------------------
__global__ void embed_kernel(const int* __restrict__ tokens,
                             const float* __restrict__ emb) {
    int idx = blockIdx.x * blockDim.x + threadIdx.x;     // over B*L*(H/4)
    if (idx >= Bd * Ld * (Hd / 4)) return;
    int t = idx >> 8;           // / (H/4)
    int q = idx & 255;
    int tok = tokens[t];
    const float4* src = (const float4*)(emb + (size_t)tok * Hd);
    ((float4*)g_h0)[idx] = src[q];
}

// ---------------------------------------------------------------------------
// 3) per-level GEMM: pre(M,5120) = A(M,2048) @ g_Wcat + g_bcat
//    A row m: batch b = m/P, pair j = m%P, contiguous 2048 floats at
//      level==0 : g_h0  + b*(L*H)   + j*2048
//      level>=1 : dout  + (off_{lvl-1} + b*255)*H + j*2048
//    128x128x8 tile, 256 threads, 8x8 microtile.
// ---------------------------------------------------------------------------
__global__ __launch_bounds__(256)
void sgemm_kernel(const float* __restrict__ dout, int level) {
    const int P = 128 >> level;
    const int M = Bd * P;
    const float* Abase;
    size_t batchStride;
    if (level == 0) {
        Abase = g_h0;
        batchStride = (size_t)Ld * Hd;
    } else {
        int off_prev = 256 - (256 >> (level - 1));
        Abase = dout + (size_t)off_prev * Hd;
        batchStride = (size_t)FOREST * Hd;
    }

    __shared__ float As[8][128];
    __shared__ float Bs[8][128];

    const int tid = threadIdx.x;
    const int blockM = blockIdx.y * 128;
    const int blockN = blockIdx.x * 128;

    // A staging: thread -> (row = tid/2, k quad = (tid&1)*4)
    const int a_row = tid >> 1;
    const int a_k = (tid & 1) * 4;
    const float* a_ptr = nullptr;
    {
        int gm = blockM + a_row;
        if (gm < M) {
            int b = gm / P;
            int j = gm - b * P;
            a_ptr = Abase + (size_t)b * batchStride + (size_t)j * KDIM + a_k;
        }
    }
    // B staging: thread -> (k = tid/32, col quad = (tid&31)*4)
    const int b_k = tid >> 5;
    const int b_col = (tid & 31) * 4;
    const float* b_ptr = g_Wcat + (size_t)b_k * NDIM + blockN + b_col;

    const int tr = (tid >> 4) * 8;   // micro-tile row offset
    const int tc = (tid & 15) * 8;   // micro-tile col offset

    float acc[8][8];
#pragma unroll
    for (int i = 0; i < 8; i++)
#pragma unroll
        for (int j = 0; j < 8; j++) acc[i][j] = 0.0f;

    for (int k0 = 0; k0 < KDIM; k0 += 8) {
        float4 av = a_ptr ? *(const float4*)(a_ptr + k0) : make_float4(0.f, 0.f, 0.f, 0.f);
        float4 bv = *(const float4*)(b_ptr + (size_t)k0 * NDIM);
        __syncthreads();
        As[a_k + 0][a_row] = av.x;
        As[a_k + 1][a_row] = av.y;
        As[a_k + 2][a_row] = av.z;
        As[a_k + 3][a_row] = av.w;
        *(float4*)&Bs[b_k][b_col] = bv;
        __syncthreads();
#pragma unroll
        for (int kk = 0; kk < 8; ++kk) {
            float4 a0 = *(const float4*)&As[kk][tr];
            float4 a1 = *(const float4*)&As[kk][tr + 4];
            float4 q0 = *(const float4*)&Bs[kk][tc];
            float4 q1 = *(const float4*)&Bs[kk][tc + 4];
            float ar[8] = {a0.x, a0.y, a0.z, a0.w, a1.x, a1.y, a1.z, a1.w};
            float br[8] = {q0.x, q0.y, q0.z, q0.w, q1.x, q1.y, q1.z, q1.w};
#pragma unroll
            for (int i = 0; i < 8; i++)
#pragma unroll
                for (int j = 0; j < 8; j++) acc[i][j] = fmaf(ar[i], br[j], acc[i][j]);
        }
    }

    // epilogue: += bias, store to g_pre
#pragma unroll
    for (int i = 0; i < 8; i++) {
        int gm = blockM + tr + i;
        if (gm >= M) continue;
        float* crow = g_pre + (size_t)gm * NDIM + blockN + tc;
#pragma unroll
        for (int j = 0; j < 8; j += 4) {
            float4 v;
            v.x = acc[i][j + 0] + g_bcat[blockN + tc + j + 0];
            v.y = acc[i][j + 1] + g_bcat[blockN + tc + j + 1];
            v.z = acc[i][j + 2] + g_bcat[blockN + tc + j + 2];
            v.w = acc[i][j + 3] + g_bcat[blockN + tc + j + 3];
            *(float4*)(crow + j) = v;
        }
    }
}

// ---------------------------------------------------------------------------
// 4) gates: c = sig(i)*tanh(ck) + sig(fl)*cl + sig(fr)*cr ; h = sig(o)*tanh(c)
//    writes h into d_out forest slice (and root h/c for the last level)
// ---------------------------------------------------------------------------
__global__ void gates_kernel(float* __restrict__ dout, int level) {
    const int P = 128 >> level;
    const int M = Bd * P;
    int idx = blockIdx.x * blockDim.x + threadIdx.x;
    if (idx >= M * Hd) return;
    int m = idx >> 10;
    int col = idx & (Hd - 1);

    const float* prow = g_pre + (size_t)m * NDIM;
    float p_i = prow[col];
    float p_o = prow[col + 1024];
    float p_k = prow[col + 2048];
    float p_fl = prow[col + 3072];
    float p_fr = prow[col + 4096];

    float cl = 0.f, cr = 0.f;
    if (level > 0) {
        const float* cp = g_cbuf[(level - 1) & 1];
        cl = cp[(size_t)m * KDIM + col];
        cr = cp[(size_t)m * KDIM + Hd + col];
    }

    float ig = sigmoidf_(p_i);
    float og = sigmoidf_(p_o);
    float ck = tanhf(p_k);
    float fl = sigmoidf_(p_fl);
    float fr = sigmoidf_(p_fr);
    float c = ig * ck + fl * cl + fr * cr;
    float h = og * tanhf(c);

    g_cbuf[level & 1][(size_t)m * Hd + col] = c;

    int b = m / P;
    int j = m - b * P;
    int off = 256 - (256 >> level);
    dout[((size_t)b * FOREST + off + j) * Hd + col] = h;

    if (level == NLVL - 1) {
        // root: m == b, P == 1. h_root (1,B,H) then c_root (1,B,H) after forest.
        float* hroot = dout + (size_t)Bd * FOREST * Hd;
        float* croot = hroot + (size_t)Bd * Hd;
        hroot[idx] = h;
        croot[idx] = c;
    }
}

// ---------------------------------------------------------------------------
// launcher (graph-capturable: kernel launches only, default stream)
// ---------------------------------------------------------------------------
extern "C" void kernel_launch(void* const* d_in, const int* in_sizes, int n_in,
                              void* d_out, int out_size) {
    const int*   tokens = (const int*)  d_in[0];
    const float* emb    = (const float*)d_in[1];
    const float* W_iock = (const float*)d_in[2];
    const float* b_iock = (const float*)d_in[3];
    const float* U_iock = (const float*)d_in[4];
    const float* W_fl   = (const float*)d_in[5];
    const float* b_fl   = (const float*)d_in[6];
    const float* U_fl   = (const float*)d_in[7];
    const float* W_fr   = (const float*)d_in[8];
    const float* b_fr   = (const float*)d_in[9];
    const float* U_fr   = (const float*)d_in[10];
    float* out = (float*)d_out;

    // pack weights + bias
    {
        size_t total = (size_t)KDIM * NDIM;
        int blocks = (int)((total + 255) / 256);
        pack_weights_kernel<<<blocks, 256>>>(W_iock, U_iock, W_fl, U_fl, W_fr, U_fr,
                                             b_iock, b_fl, b_fr);
    }
    // embedding gather
    {
        int total = Bd * Ld * (Hd / 4);
        embed_kernel<<<(total + 255) / 256, 256>>>(tokens, emb);
    }
    // level sweep
    for (int level = 0; level < NLVL; ++level) {
        int P = 128 >> level;
        int M = Bd * P;
        dim3 grid(NDIM / 128, (M + 127) / 128);
        sgemm_kernel<<<grid, 256>>>(out, level);
        int total = M * Hd;
        gates_kernel<<<(total + 255) / 256, 256>>>(out, level);
    }
}

// round 4
// speedup vs baseline: 1.0016x; 1.0016x over previous
#include <cuda_runtime.h>
#include <cuda_bf16.h>
#include <math.h>

// Problem constants
#define Hd     1024
#define Bd     64
#define Ld     256
#define KDIM   2048          // 2*H  (hl | hr)
#define NDIM   5120          // 5*H  (i | o | ck | fl | fr)
#define NLVL   8             // 256 -> 1
#define FOREST 255           // nodes per batch in forest_output

// ---- static device scratch (no allocations allowed) ----
__device__ float g_Wcat[(size_t)KDIM * NDIM];                 // packed weights (2048 x 5120)
__device__ float g_bcat[NDIM];                                // packed bias
__device__ float g_h0[(size_t)Bd * Ld * Hd];                  // level-0 input (embeddings)
__device__ float g_pre[(size_t)(Bd * Ld / 2) * NDIM];         // GEMM output, max M = 8192
__device__ float g_cbuf[2][(size_t)Bd * (Ld / 2) * Hd];       // c ping-pong

__device__ __forceinline__ float sigmoidf_(float x) {
    return 1.0f / (1.0f + expf(-x));
}

// ---------------------------------------------------------------------------
// 1) pack weights: Wcat[k][n]  (k<1024: W rows, else U rows; n: [iock|fl|fr])
// ---------------------------------------------------------------------------
__global__ void pack_weights_kernel(const float* __restrict__ W_iock,
                                    const float* __restrict__ U_iock,
                                    const float* __restrict__ W_fl,
                                    const float* __restrict__ U_fl,
                                    const float* __restrict__ W_fr,
                                    const float* __restrict__ U_fr,
                                    const float* __restrict__ b_iock,
                                    const float* __restrict__ b_fl,
                                    const float* __restrict__ b_fr) {
    size_t idx = (size_t)blockIdx.x * blockDim.x + threadIdx.x;
    if (idx >= (size_t)KDIM * NDIM) return;
    int n = (int)(idx % NDIM);
    int k = (int)(idx / NDIM);
    bool isW = (k < Hd);
    int kr = isW ? k : (k - Hd);
    float v;
    if (n < 3 * Hd) {
        v = isW ? W_iock[(size_t)kr * (3 * Hd) + n] : U_iock[(size_t)kr * (3 * Hd) + n];
    } else if (n < 4 * Hd) {
        int nn = n - 3 * Hd;
        v = isW ? W_fl[(size_t)kr * Hd + nn] : U_fl[(size_t)kr * Hd + nn];
    } else {
        int nn = n - 4 * Hd;
        v = isW ? W_fr[(size_t)kr * Hd + nn] : U_fr[(size_t)kr * Hd + nn];
    }
    g_Wcat[idx] = v;
    if (idx < NDIM) {
        int nb = (int)idx;
        g_bcat[nb] = (nb < 3 * Hd) ? b_iock[nb]
                   : (nb < 4 * Hd) ? b_fl[nb - 3 * Hd]
                                   : b_fr[nb - 4 * Hd];
    }
}

// ---------------------------------------------------------------------------
// 2) embedding gather: g_h0[b, l, :] = emb[tokens[b,l], :]   (float4 vectorized)
// ---------------------------------------------------------------------------
__global__ void embed_kernel(const int* __restrict__ tokens,
                             const float* __restrict__ emb) {
    int idx = blockIdx.x * blockDim.x + threadIdx.x;     // over B*L*(H/4)
    if (idx >= Bd * Ld * (Hd / 4)) return;
    int t = idx >> 8;           // / (H/4)
    int q = idx & 255;
    int tok = tokens[t];
    const float4* src = (const float4*)(emb + (size_t)tok * Hd);
    ((float4*)g_h0)[idx] = src[q];
}

// ---------------------------------------------------------------------------
// 3) per-level GEMM: pre(M,5120) = A(M,2048) @ g_Wcat + g_bcat
//    A row m: batch b = m/P, pair j = m%P, contiguous 2048 floats at
//      level==0 : g_h0  + b*(L*H)   + j*2048
//      level>=1 : dout  + (off_{lvl-1} + b*255)*H + j*2048
//    128x128x8 tile, 256 threads, 8x8 microtile.
// ---------------------------------------------------------------------------
__global__ __launch_bounds__(256)
void sgemm_kernel(const float* __restrict__ dout, int level) {
    const int P = 128 >> level;
    const int M = Bd * P;
    const float* Abase;
    size_t batchStride;
    if (level == 0) {
        Abase = g_h0;
        batchStride = (size_t)Ld * Hd;
    } else {
        int off_prev = 256 - (256 >> (level - 1));
        Abase = dout + (size_t)off_prev * Hd;
        batchStride = (size_t)FOREST * Hd;
    }

    __shared__ float As[8][128];
    __shared__ float Bs[8][128];

    const int tid = threadIdx.x;
    const int blockM = blockIdx.y * 128;
    const int blockN = blockIdx.x * 128;

    // A staging: thread -> (row = tid/2, k quad = (tid&1)*4)
    const int a_row = tid >> 1;
    const int a_k = (tid & 1) * 4;
    const float* a_ptr = nullptr;
    {
        int gm = blockM + a_row;
        if (gm < M) {
            int b = gm / P;
            int j = gm - b * P;
            a_ptr = Abase + (size_t)b * batchStride + (size_t)j * KDIM + a_k;
        }
    }
    // B staging: thread -> (k = tid/32, col quad = (tid&31)*4)
    const int b_k = tid >> 5;
    const int b_col = (tid & 31) * 4;
    const float* b_ptr = g_Wcat + (size_t)b_k * NDIM + blockN + b_col;

    const int tr = (tid >> 4) * 8;   // micro-tile row offset
    const int tc = (tid & 15) * 8;   // micro-tile col offset

    float acc[8][8];
#pragma unroll
    for (int i = 0; i < 8; i++)
#pragma unroll
        for (int j = 0; j < 8; j++) acc[i][j] = 0.0f;

    for (int k0 = 0; k0 < KDIM; k0 += 8) {
        float4 av = a_ptr ? *(const float4*)(a_ptr + k0) : make_float4(0.f, 0.f, 0.f, 0.f);
        float4 bv = *(const float4*)(b_ptr + (size_t)k0 * NDIM);
        __syncthreads();
        As[a_k + 0][a_row] = av.x;
        As[a_k + 1][a_row] = av.y;
        As[a_k + 2][a_row] = av.z;
        As[a_k + 3][a_row] = av.w;
        *(float4*)&Bs[b_k][b_col] = bv;
        __syncthreads();
#pragma unroll
        for (int kk = 0; kk < 8; ++kk) {
            float4 a0 = *(const float4*)&As[kk][tr];
            float4 a1 = *(const float4*)&As[kk][tr + 4];
            float4 q0 = *(const float4*)&Bs[kk][tc];
            float4 q1 = *(const float4*)&Bs[kk][tc + 4];
            float ar[8] = {a0.x, a0.y, a0.z, a0.w, a1.x, a1.y, a1.z, a1.w};
            float br[8] = {q0.x, q0.y, q0.z, q0.w, q1.x, q1.y, q1.z, q1.w};
#pragma unroll
            for (int i = 0; i < 8; i++)
#pragma unroll
                for (int j = 0; j < 8; j++) acc[i][j] = fmaf(ar[i], br[j], acc[i][j]);
        }
    }

    // epilogue: += bias, store to g_pre
#pragma unroll
    for (int i = 0; i < 8; i++) {
        int gm = blockM + tr + i;
        if (gm >= M) continue;
        float* crow = g_pre + (size_t)gm * NDIM + blockN + tc;
#pragma unroll
        for (int j = 0; j < 8; j += 4) {
            float4 v;
            v.x = acc[i][j + 0] + g_bcat[blockN + tc + j + 0];
            v.y = acc[i][j + 1] + g_bcat[blockN + tc + j + 1];
            v.z = acc[i][j + 2] + g_bcat[blockN + tc + j + 2];
            v.w = acc[i][j + 3] + g_bcat[blockN + tc + j + 3];
            *(float4*)(crow + j) = v;
        }
    }
}

// ---------------------------------------------------------------------------
// 4) gates: c = sig(i)*tanh(ck) + sig(fl)*cl + sig(fr)*cr ; h = sig(o)*tanh(c)
//    writes h into d_out forest slice (and root h/c for the last level)
// ---------------------------------------------------------------------------
__global__ void gates_kernel(float* __restrict__ dout, int level) {
    const int P = 128 >> level;
    const int M = Bd * P;
    int idx = blockIdx.x * blockDim.x + threadIdx.x;
    if (idx >= M * Hd) return;
    int m = idx >> 10;
    int col = idx & (Hd - 1);

    const float* prow = g_pre + (size_t)m * NDIM;
    float p_i = prow[col];
    float p_o = prow[col + 1024];
    float p_k = prow[col + 2048];
    float p_fl = prow[col + 3072];
    float p_fr = prow[col + 4096];

    float cl = 0.f, cr = 0.f;
    if (level > 0) {
        const float* cp = g_cbuf[(level - 1) & 1];
        cl = cp[(size_t)m * KDIM + col];
        cr = cp[(size_t)m * KDIM + Hd + col];
    }

    float ig = sigmoidf_(p_i);
    float og = sigmoidf_(p_o);
    float ck = tanhf(p_k);
    float fl = sigmoidf_(p_fl);
    float fr = sigmoidf_(p_fr);
    float c = ig * ck + fl * cl + fr * cr;
    float h = og * tanhf(c);

    g_cbuf[level & 1][(size_t)m * Hd + col] = c;

    int b = m / P;
    int j = m - b * P;
    int off = 256 - (256 >> level);
    dout[((size_t)b * FOREST + off + j) * Hd + col] = h;

    if (level == NLVL - 1) {
        // root: m == b, P == 1. h_root (1,B,H) then c_root (1,B,H) after forest.
        float* hroot = dout + (size_t)Bd * FOREST * Hd;
        float* croot = hroot + (size_t)Bd * Hd;
        hroot[idx] = h;
        croot[idx] = c;
    }
}

// ---------------------------------------------------------------------------
// launcher (graph-capturable: kernel launches only, default stream)
// ---------------------------------------------------------------------------
extern "C" void kernel_launch(void* const* d_in, const int* in_sizes, int n_in,
                              void* d_out, int out_size) {
    const int*   tokens = (const int*)  d_in[0];
    const float* emb    = (const float*)d_in[1];
    const float* W_iock = (const float*)d_in[2];
    const float* b_iock = (const float*)d_in[3];
    const float* U_iock = (const float*)d_in[4];
    const float* W_fl   = (const float*)d_in[5];
    const float* b_fl   = (const float*)d_in[6];
    const float* U_fl   = (const float*)d_in[7];
    const float* W_fr   = (const float*)d_in[8];
    const float* b_fr   = (const float*)d_in[9];
    const float* U_fr   = (const float*)d_in[10];
    float* out = (float*)d_out;

    // pack weights + bias
    {
        size_t total = (size_t)KDIM * NDIM;
        int blocks = (int)((total + 255) / 256);
        pack_weights_kernel<<<blocks, 256>>>(W_iock, U_iock, W_fl, U_fl, W_fr, U_fr,
                                             b_iock, b_fl, b_fr);
    }
    // embedding gather
    {
        int total = Bd * Ld * (Hd / 4);
        embed_kernel<<<(total + 255) / 256, 256>>>(tokens, emb);
    }
    // level sweep
    for (int level = 0; level < NLVL; ++level) {
        int P = 128 >> level;
        int M = Bd * P;
        dim3 grid(NDIM / 128, (M + 127) / 128);
        sgemm_kernel<<<grid, 256>>>(out, level);
        int total = M * Hd;
        gates_kernel<<<(total + 255) / 256, 256>>>(out, level);
    }
}